// round 5
// baseline (speedup 1.0000x reference)
#include <cuda_runtime.h>

#define CG 16
#define HH 64
#define WW 64
#define HW 4096
#define GSTR (CG*HW)
#define NT 256
#define NGROUPS 512
#define TSTR 72
#define TROWS 68
#define TILEF (TROWS*TSTR)
#define NBUF 3

__device__ __forceinline__ float sigf(float x){ return 1.0f/(1.0f+__expf(-x)); }

__device__ __forceinline__ void cp_tile_async(float* sbuf, const float* src, int tid){
  // 4096 floats = 1024 float4; each thread copies 4 float4s into rows 2..65, col offset 4
  #pragma unroll
  for (int k = 0; k < 4; ++k) {
    int f = tid + NT*k;                 // float4 index 0..1023
    int h = f >> 4, w4 = f & 15;
    float* dst = sbuf + (h+2)*TSTR + 4 + w4*4;
    unsigned daddr = (unsigned)__cvta_generic_to_shared(dst);
    const float4* s = reinterpret_cast<const float4*>(src) + f;
    asm volatile("cp.async.cg.shared.global [%0], [%1], 16;\n" :: "r"(daddr), "l"(s));
  }
}

__global__ __launch_bounds__(NT) void ema_kernel(
    const float* __restrict__ x,
    const float* __restrict__ w1, const float* __restrict__ b1,
    const float* __restrict__ w3, const float* __restrict__ b3,
    const float* __restrict__ w5, const float* __restrict__ b5,
    const float* __restrict__ gnw, const float* __restrict__ gnb,
    const float* __restrict__ ecw, const float* __restrict__ ecb,
    float* __restrict__ out)
{
  __shared__ float s_xh[CG*HH];       // row means
  __shared__ float s_xw[CG*WW];       // col means
  __shared__ float s_sh[CG*HH];       // sigmoid h-gate; later k1*gate
  __shared__ float s_sw[CG*WW];       // sigmoid w-gate
  __shared__ float s_w1[CG*CG];
  __shared__ float s_sum[CG], s_sum2[CG];
  __shared__ float s_rect[CG][25];
  __shared__ float s_m1[CG], s_m2[CG], s_m3[CG];
  __shared__ float s_s[3][CG], s_e[3][CG];
  __shared__ float s_a2[CG], s_a3[CG];
  __shared__ float s_mu[CG], s_inv[CG];
  __shared__ float s_k1[CG], s_ca[CG], s_c1p[CG];
  __shared__ float s_Wc[CG][25];
  __shared__ float s_cst;
  extern __shared__ float s_tiles[];  // NBUF * TILEF floats, zero-padded halo

  const int g = blockIdx.x;
  const int tid = threadIdx.x;
  const int lane = tid & 31;
  const int wid = tid >> 5;
  const float* gx = x + (size_t)g * GSTR;
  float* gout = out + (size_t)g * GSTR;
  const float4* gx4 = reinterpret_cast<const float4*>(gx);

  // ---- init: zero all tile buffers (halo must stay 0), small arrays ----
  if (tid < CG) { s_sum[tid] = 0.f; s_sum2[tid] = 0.f; }
  for (int i = tid; i < NBUF*TILEF; i += NT) s_tiles[i] = 0.f;
  if (tid < CG*CG) s_w1[tid] = w1[tid];
  __syncthreads();

  // ---- prefetch tiles 0,1 (overlap all of phases A-D) ----
  cp_tile_async(s_tiles,          gx,      tid);
  asm volatile("cp.async.commit_group;\n");
  cp_tile_async(s_tiles + TILEF,  gx + HW, tid);
  asm volatile("cp.async.commit_group;\n");

  // ---- Phase A1: row means (coalesced float4, 16-lane segmented reduce) ----
  for (int k = 0; k < 64; ++k) {
    int idx = tid + NT*k;                       // float4 index, 0..16383
    float4 v = gx4[idx];
    float s = (v.x+v.y)+(v.z+v.w);
    s += __shfl_xor_sync(0xffffffffu, s, 8);
    s += __shfl_xor_sync(0xffffffffu, s, 4);
    s += __shfl_xor_sync(0xffffffffu, s, 2);
    s += __shfl_xor_sync(0xffffffffu, s, 1);
    if ((lane & 15) == 0) s_xh[idx >> 4] = s * (1.0f/WW);
  }
  // ---- Phase A2: col means (second read hits L2) ----
  for (int k = 0; k < 4; ++k) {
    int cidx = tid + NT*k;                      // ci*64 + w
    int ci = cidx >> 6, w = cidx & 63;
    const float* p = gx + ci*HW + w;
    float s = 0.f;
    #pragma unroll 16
    for (int h = 0; h < HH; ++h) s += p[h*WW];
    s_xw[cidx] = s * (1.0f/HH);
  }
  __syncthreads();

  // ---- Phase B: 1x1 conv over channel dim on [x_h ; x_w], sigmoid gates ----
  for (int k = 0; k < 8; ++k) {
    int o = tid + NT*k;                         // c*128 + p
    int c = o >> 7, p = o & 127;
    float acc = b1[c];
    const float* src = (p < HH) ? (s_xh + p) : (s_xw + (p - HH));
    #pragma unroll
    for (int ci = 0; ci < CG; ++ci) acc += s_w1[c*CG+ci] * src[ci*64];
    float sgm = sigf(acc);
    if (p < HH) s_sh[c*HH + p] = sgm; else s_sw[c*WW + (p-HH)] = sgm;
  }
  __syncthreads();

  // ---- Phase C: per-channel sums of gated = x*sh*sw (for instance-norm) ----
  {
    float ls = 0.f, ls2 = 0.f;
    for (int k = 0; k < 64; ++k) {
      int idx = tid + NT*k;
      int ci = k >> 2;                          // all threads share ci at given k
      int h = (idx >> 4) & 63;
      int w4 = idx & 15;
      float4 v = gx4[idx];
      float shv = s_sh[ci*HH + h];
      const float* swp = s_sw + ci*WW + w4*4;
      float g0 = v.x*shv*swp[0];
      float g1 = v.y*shv*swp[1];
      float g2 = v.z*shv*swp[2];
      float g3 = v.w*shv*swp[3];
      ls  += (g0+g1)+(g2+g3);
      ls2 += (g0*g0+g1*g1)+(g2*g2+g3*g3);
      if ((k & 3) == 3) {
        #pragma unroll
        for (int off = 16; off > 0; off >>= 1) {
          ls  += __shfl_xor_sync(0xffffffffu, ls,  off);
          ls2 += __shfl_xor_sync(0xffffffffu, ls2, off);
        }
        if (lane == 0) { atomicAdd(&s_sum[ci], ls); atomicAdd(&s_sum2[ci], ls2); }
        ls = 0.f; ls2 = 0.f;
      }
    }
  }
  __syncthreads();

  // ---- Phase D1: rectangle sums for all 25 shifts + stats ----
  if (tid < CG) {
    int ci = tid;
    float T = 0.f;
    #pragma unroll
    for (int h = 0; h < HH; ++h) T += s_xh[ci*HH + h];
    T *= (float)WW;
    float rs[4] = { s_xh[ci*HH+0]*WW, s_xh[ci*HH+1]*WW, s_xh[ci*HH+62]*WW, s_xh[ci*HH+63]*WW };
    float cs[4] = { s_xw[ci*WW+0]*HH, s_xw[ci*WW+1]*HH, s_xw[ci*WW+62]*HH, s_xw[ci*WW+63]*HH };
    const int RB[4] = {0,1,62,63};
    float corn[4][4];
    for (int a=0;a<4;++a)
      for (int b=0;b<4;++b)
        corn[a][b] = gx[ci*HW + RB[a]*WW + RB[b]];
    const int msk[5] = {0xC, 0x8, 0x0, 0x1, 0x3};
    float rex[5], cex[5];
    for (int j=0;j<5;++j) {
      float r=0.f, c=0.f;
      for (int b=0;b<4;++b) if ((msk[j]>>b)&1) { r += rs[b]; c += cs[b]; }
      rex[j]=r; cex[j]=c;
    }
    for (int jh=0;jh<5;++jh)
      for (int jw=0;jw<5;++jw) {
        float r = T - rex[jh] - cex[jw];
        for (int a=0;a<4;++a) if ((msk[jh]>>a)&1)
          for (int b=0;b<4;++b) if ((msk[jw]>>b)&1)
            r += corn[a][b];
        s_rect[ci][jh*5+jw] = r;
      }
    float mu  = s_sum[ci]  * (1.0f/HW);
    float var = s_sum2[ci] * (1.0f/HW) - mu*mu;
    s_mu[ci]  = mu;
    s_inv[ci] = rsqrtf(var + 1e-5f);
  }
  __syncthreads();

  // ---- Phase D3: channel means ----
  if (tid < CG) {
    int c = tid;
    float a2acc = 0.f, a3acc = 0.f;
    for (int ci = 0; ci < CG; ++ci) {
      const float* w3p = w3 + (c*CG + ci)*9;
      const float* w5p = w5 + (c*CG + ci)*25;
      #pragma unroll
      for (int kh=0;kh<3;++kh)
        #pragma unroll
        for (int kw=0;kw<3;++kw)
          a2acc += w3p[kh*3+kw] * s_rect[ci][(kh+1)*5 + (kw+1)];
      #pragma unroll
      for (int kk=0;kk<25;++kk) a3acc += w5p[kk] * s_rect[ci][kk];
    }
    s_m1[c] = gnb[c];
    s_m2[c] = a2acc * (1.0f/HW) + b3[c];
    s_m3[c] = a3acc * (1.0f/HW) + b5[c];
  }
  __syncthreads();

  // ---- Phase D4: softmax + eca on each of the 3 mean vectors ----
  if (tid < 48) {
    int j = tid >> 4, c = tid & 15;
    const float* m = (j==0) ? s_m1 : ((j==1) ? s_m2 : s_m3);
    float mx = m[0];
    for (int i=1;i<CG;++i) mx = fmaxf(mx, m[i]);
    float sum = 0.f;
    for (int i=0;i<CG;++i) sum += __expf(m[i]-mx);
    s_s[j][c] = __expf(m[c]-mx) / sum;
    float prev = (c>0)     ? m[c-1] : 0.f;
    float nxt  = (c<CG-1)  ? m[c+1] : 0.f;
    s_e[j][c] = sigf(ecw[0]*prev + ecw[1]*m[c] + ecw[2]*nxt + ecb[0]);
  }
  __syncthreads();

  // ---- Phase D5: coefficients ----
  if (tid < CG) {
    int c = tid;
    s_ca[c] = s_e[0][c] + s_e[1][c] + s_e[2][c];
    float a1 = s_s[1][c] + s_s[2][c];
    float a2 = s_s[0][c] + s_s[2][c];
    float a3 = s_s[0][c] + s_s[1][c];
    s_a2[c] = a2; s_a3[c] = a3;
    float iv = s_inv[c]*gnw[c];
    s_k1[c]  = a1 * iv;
    s_c1p[c] = a1*(gnb[c] - s_mu[c]*iv) + a2*b3[c] + a3*b5[c];
  }
  __syncthreads();
  if (tid == 0) {
    float cst = 0.f;
    for (int c=0;c<CG;++c) cst += s_c1p[c];
    s_cst = cst;
  }
  // ---- Phase D6: effective single-output 5x5 kernel ----
  for (int o = tid; o < CG*25; o += NT) {
    int ci = o / 25, k = o % 25;
    int dh = k / 5, dw = k % 5;
    float wv = 0.f;
    for (int c=0;c<CG;++c) wv += s_a3[c] * w5[(c*CG+ci)*25 + k];
    if (dh>=1 && dh<=3 && dw>=1 && dw<=3) {
      int k3 = (dh-1)*3 + (dw-1);
      for (int c=0;c<CG;++c) wv += s_a2[c] * w3[(c*CG+ci)*9 + k3];
    }
    s_Wc[ci][k] = wv;
  }
  // ---- Phase D7: fold k1 into h-gate ----
  for (int o = tid; o < CG*HH; o += NT) {
    int ci = o >> 6;
    s_sh[o] *= s_k1[ci];
  }

  // ---- Phase E: row-pair conv, triple-buffered cp.async (depth-2 prefetch) ----
  // warp wid owns output rows h0..h0+7; lane owns cols lane, lane+32.
  float acc[16];
  #pragma unroll
  for (int i=0;i<16;++i) acc[i] = 0.f;
  const int h0 = wid * 8;

  for (int ci = 0; ci < CG; ++ci) {
    __syncthreads();                            // buffer (ci+2)%NBUF free to refill
    if (ci + 2 < CG) {
      cp_tile_async(s_tiles + ((ci+2)%NBUF)*TILEF, gx + (ci+2)*HW, tid);
      asm volatile("cp.async.commit_group;\n");
      asm volatile("cp.async.wait_group 2;\n"); // tile ci arrived
    } else if (ci + 1 < CG) {
      asm volatile("cp.async.wait_group 1;\n");
    } else {
      asm volatile("cp.async.wait_group 0;\n");
    }
    __syncthreads();                            // tile[ci%NBUF] visible to all

    const float* tile = s_tiles + (ci%NBUF)*TILEF;
    float wc[25];
    #pragma unroll
    for (int k=0;k<25;++k) wc[k] = s_Wc[ci][k];
    float sw0 = s_sw[ci*WW + lane];
    float sw1 = s_sw[ci*WW + lane + 32];
    #pragma unroll
    for (int jp = 0; jp < 4; ++jp) {            // row pairs: shared 6-row window
      int h = h0 + jp*2;
      float kh0 = s_sh[ci*HH + h];
      float kh1 = s_sh[ci*HH + h + 1];
      float a00=0.f,a01=0.f,a10=0.f,a11=0.f;
      #pragma unroll
      for (int r = 0; r < 6; ++r) {
        const float* trow = tile + (h + r)*TSTR + 2;
        float v0[5], v1[5];
        #pragma unroll
        for (int d=0; d<5; ++d) { v0[d] = trow[lane + d]; v1[d] = trow[lane + 32 + d]; }
        if (r < 5) {
          #pragma unroll
          for (int d=0; d<5; ++d) { a00 += wc[r*5+d]*v0[d]; a01 += wc[r*5+d]*v1[d]; }
        }
        if (r >= 1) {
          #pragma unroll
          for (int d=0; d<5; ++d) { a10 += wc[(r-1)*5+d]*v0[d]; a11 += wc[(r-1)*5+d]*v1[d]; }
        }
      }
      float c00 = tile[(h+2)*TSTR + 4 + lane];
      float c01 = tile[(h+2)*TSTR + 4 + lane + 32];
      float c10 = tile[(h+3)*TSTR + 4 + lane];
      float c11 = tile[(h+3)*TSTR + 4 + lane + 32];
      a00 += kh0*sw0*c00;  a01 += kh0*sw1*c01;
      a10 += kh1*sw0*c10;  a11 += kh1*sw1*c11;
      acc[jp*4+0]+=a00; acc[jp*4+1]+=a01; acc[jp*4+2]+=a10; acc[jp*4+3]+=a11;
    }
  }

  // ---- Phase F: out = x * ca[ci] * sigmoid(wsum) ----
  float cst = s_cst;
  float wv[16];
  #pragma unroll
  for (int i=0;i<16;++i) wv[i] = sigf(acc[i] + cst);
  for (int ci = 0; ci < CG; ++ci) {
    float cav = s_ca[ci];
    #pragma unroll
    for (int jp=0;jp<4;++jp) {
      int h = h0 + jp*2;
      int b = ci*HW + h*WW + lane;
      gout[b]    = gx[b]    * (cav * wv[jp*4+0]);
      gout[b+32] = gx[b+32] * (cav * wv[jp*4+1]);
      gout[b+64] = gx[b+64] * (cav * wv[jp*4+2]);
      gout[b+96] = gx[b+96] * (cav * wv[jp*4+3]);
    }
  }
}

extern "C" void kernel_launch(void* const* d_in, const int* in_sizes, int n_in,
                              void* d_out, int out_size) {
  (void)in_sizes; (void)n_in; (void)out_size;
  const int dyn_smem = NBUF * TILEF * sizeof(float);   // 58752 B -> 2 CTAs/SM
  cudaFuncSetAttribute(ema_kernel, cudaFuncAttributeMaxDynamicSharedMemorySize, dyn_smem);
  ema_kernel<<<NGROUPS, NT, dyn_smem>>>(
      (const float*)d_in[0],
      (const float*)d_in[1], (const float*)d_in[2],
      (const float*)d_in[3], (const float*)d_in[4],
      (const float*)d_in[5], (const float*)d_in[6],
      (const float*)d_in[7], (const float*)d_in[8],
      (const float*)d_in[9], (const float*)d_in[10],
      (float*)d_out);
}

// round 6
// speedup vs baseline: 1.7316x; 1.7316x over previous
#include <cuda_runtime.h>

#define CG 16
#define HH 64
#define WW 64
#define HW 4096
#define GSTR (CG*HW)
#define NT 256
#define NGROUPS 512
#define TSTR 72
#define TROWS 68
#define TILEF (TROWS*TSTR)
#define DYN_BYTES 61440   /* tile (19584B) + pad: forces smem-limited 2 CTAs/SM */

__device__ __forceinline__ float sigf(float x){ return 1.0f/(1.0f+__expf(-x)); }

__global__ __launch_bounds__(NT) void ema_kernel(
    const float* __restrict__ x,
    const float* __restrict__ w1, const float* __restrict__ b1,
    const float* __restrict__ w3, const float* __restrict__ b3,
    const float* __restrict__ w5, const float* __restrict__ b5,
    const float* __restrict__ gnw, const float* __restrict__ gnb,
    const float* __restrict__ ecw, const float* __restrict__ ecb,
    float* __restrict__ out)
{
  __shared__ float s_xh[CG*HH];       // row means
  __shared__ float s_xw[CG*WW];       // col means
  __shared__ float s_sh[CG*HH];       // sigmoid h-gate; later k1*gate
  __shared__ float s_sw[CG*WW];       // sigmoid w-gate
  __shared__ float s_w1[CG*CG];
  __shared__ float s_sum[CG], s_sum2[CG];
  __shared__ float s_rect[CG][25];
  __shared__ float s_m1[CG], s_m2[CG], s_m3[CG];
  __shared__ float s_s[3][CG], s_e[3][CG];
  __shared__ float s_a2[CG], s_a3[CG];
  __shared__ float s_mu[CG], s_inv[CG];
  __shared__ float s_k1[CG], s_ca[CG], s_c1p[CG];
  __shared__ float s_Wc[CG][25];
  __shared__ float s_cst;
  extern __shared__ float s_tile[];   // TILEF used; rest is occupancy pad

  const int g = blockIdx.x;
  const int tid = threadIdx.x;
  const int lane = tid & 31;
  const int wid = tid >> 5;
  const float* gx = x + (size_t)g * GSTR;
  float* gout = out + (size_t)g * GSTR;
  const float4* gx4 = reinterpret_cast<const float4*>(gx);

  // ---- init ----
  if (tid < CG) { s_sum[tid] = 0.f; s_sum2[tid] = 0.f; }
  for (int i = tid; i < TILEF; i += NT) s_tile[i] = 0.f;  // halo stays 0
  if (tid < CG*CG) s_w1[tid] = w1[tid];

  // ---- Phase A1: row means (coalesced float4, 16-lane segmented reduce) ----
  for (int k = 0; k < 64; ++k) {
    int idx = tid + NT*k;                       // float4 index, 0..16383
    float4 v = gx4[idx];
    float s = (v.x+v.y)+(v.z+v.w);
    s += __shfl_xor_sync(0xffffffffu, s, 8);
    s += __shfl_xor_sync(0xffffffffu, s, 4);
    s += __shfl_xor_sync(0xffffffffu, s, 2);
    s += __shfl_xor_sync(0xffffffffu, s, 1);
    if ((lane & 15) == 0) s_xh[idx >> 4] = s * (1.0f/WW);
  }
  // ---- Phase A2: col means (second read hits L2) ----
  for (int k = 0; k < 4; ++k) {
    int cidx = tid + NT*k;                      // ci*64 + w
    int ci = cidx >> 6, w = cidx & 63;
    const float* p = gx + ci*HW + w;
    float s = 0.f;
    #pragma unroll 16
    for (int h = 0; h < HH; ++h) s += p[h*WW];
    s_xw[cidx] = s * (1.0f/HH);
  }
  __syncthreads();

  // ---- Phase B: 1x1 conv over channel dim on [x_h ; x_w], sigmoid gates ----
  for (int k = 0; k < 8; ++k) {
    int o = tid + NT*k;                         // c*128 + p
    int c = o >> 7, p = o & 127;
    float acc = b1[c];
    const float* src = (p < HH) ? (s_xh + p) : (s_xw + (p - HH));
    #pragma unroll
    for (int ci = 0; ci < CG; ++ci) acc += s_w1[c*CG+ci] * src[ci*64];
    float sgm = sigf(acc);
    if (p < HH) s_sh[c*HH + p] = sgm; else s_sw[c*WW + (p-HH)] = sgm;
  }
  __syncthreads();

  // ---- Phase C: per-channel sums of gated = x*sh*sw (for instance-norm) ----
  {
    float ls = 0.f, ls2 = 0.f;
    for (int k = 0; k < 64; ++k) {
      int idx = tid + NT*k;
      int ci = k >> 2;                          // all threads share ci at given k
      int h = (idx >> 4) & 63;
      int w4 = idx & 15;
      float4 v = gx4[idx];
      float shv = s_sh[ci*HH + h];
      const float* swp = s_sw + ci*WW + w4*4;
      float g0 = v.x*shv*swp[0];
      float g1 = v.y*shv*swp[1];
      float g2 = v.z*shv*swp[2];
      float g3 = v.w*shv*swp[3];
      ls  += (g0+g1)+(g2+g3);
      ls2 += (g0*g0+g1*g1)+(g2*g2+g3*g3);
      if ((k & 3) == 3) {
        #pragma unroll
        for (int off = 16; off > 0; off >>= 1) {
          ls  += __shfl_xor_sync(0xffffffffu, ls,  off);
          ls2 += __shfl_xor_sync(0xffffffffu, ls2, off);
        }
        if (lane == 0) { atomicAdd(&s_sum[ci], ls); atomicAdd(&s_sum2[ci], ls2); }
        ls = 0.f; ls2 = 0.f;
      }
    }
  }
  __syncthreads();

  // ---- Phase D1: rectangle sums for all 25 shifts + stats ----
  if (tid < CG) {
    int ci = tid;
    float T = 0.f;
    #pragma unroll
    for (int h = 0; h < HH; ++h) T += s_xh[ci*HH + h];
    T *= (float)WW;
    float rs[4] = { s_xh[ci*HH+0]*WW, s_xh[ci*HH+1]*WW, s_xh[ci*HH+62]*WW, s_xh[ci*HH+63]*WW };
    float cs[4] = { s_xw[ci*WW+0]*HH, s_xw[ci*WW+1]*HH, s_xw[ci*WW+62]*HH, s_xw[ci*WW+63]*HH };
    const int RB[4] = {0,1,62,63};
    float corn[4][4];
    for (int a=0;a<4;++a)
      for (int b=0;b<4;++b)
        corn[a][b] = gx[ci*HW + RB[a]*WW + RB[b]];
    const int msk[5] = {0xC, 0x8, 0x0, 0x1, 0x3};
    float rex[5], cex[5];
    for (int j=0;j<5;++j) {
      float r=0.f, c=0.f;
      for (int b=0;b<4;++b) if ((msk[j]>>b)&1) { r += rs[b]; c += cs[b]; }
      rex[j]=r; cex[j]=c;
    }
    for (int jh=0;jh<5;++jh)
      for (int jw=0;jw<5;++jw) {
        float r = T - rex[jh] - cex[jw];
        for (int a=0;a<4;++a) if ((msk[jh]>>a)&1)
          for (int b=0;b<4;++b) if ((msk[jw]>>b)&1)
            r += corn[a][b];
        s_rect[ci][jh*5+jw] = r;
      }
    float mu  = s_sum[ci]  * (1.0f/HW);
    float var = s_sum2[ci] * (1.0f/HW) - mu*mu;
    s_mu[ci]  = mu;
    s_inv[ci] = rsqrtf(var + 1e-5f);
  }
  __syncthreads();

  // ---- Phase D3: channel means ----
  if (tid < CG) {
    int c = tid;
    float a2acc = 0.f, a3acc = 0.f;
    for (int ci = 0; ci < CG; ++ci) {
      const float* w3p = w3 + (c*CG + ci)*9;
      const float* w5p = w5 + (c*CG + ci)*25;
      #pragma unroll
      for (int kh=0;kh<3;++kh)
        #pragma unroll
        for (int kw=0;kw<3;++kw)
          a2acc += w3p[kh*3+kw] * s_rect[ci][(kh+1)*5 + (kw+1)];
      #pragma unroll
      for (int kk=0;kk<25;++kk) a3acc += w5p[kk] * s_rect[ci][kk];
    }
    s_m1[c] = gnb[c];
    s_m2[c] = a2acc * (1.0f/HW) + b3[c];
    s_m3[c] = a3acc * (1.0f/HW) + b5[c];
  }
  __syncthreads();

  // ---- Phase D4: softmax + eca on each of the 3 mean vectors ----
  if (tid < 48) {
    int j = tid >> 4, c = tid & 15;
    const float* m = (j==0) ? s_m1 : ((j==1) ? s_m2 : s_m3);
    float mx = m[0];
    for (int i=1;i<CG;++i) mx = fmaxf(mx, m[i]);
    float sum = 0.f;
    for (int i=0;i<CG;++i) sum += __expf(m[i]-mx);
    s_s[j][c] = __expf(m[c]-mx) / sum;
    float prev = (c>0)     ? m[c-1] : 0.f;
    float nxt  = (c<CG-1)  ? m[c+1] : 0.f;
    s_e[j][c] = sigf(ecw[0]*prev + ecw[1]*m[c] + ecw[2]*nxt + ecb[0]);
  }
  __syncthreads();

  // ---- Phase D5: coefficients ----
  if (tid < CG) {
    int c = tid;
    s_ca[c] = s_e[0][c] + s_e[1][c] + s_e[2][c];
    float a1 = s_s[1][c] + s_s[2][c];
    float a2 = s_s[0][c] + s_s[2][c];
    float a3 = s_s[0][c] + s_s[1][c];
    s_a2[c] = a2; s_a3[c] = a3;
    float iv = s_inv[c]*gnw[c];
    s_k1[c]  = a1 * iv;
    s_c1p[c] = a1*(gnb[c] - s_mu[c]*iv) + a2*b3[c] + a3*b5[c];
  }
  __syncthreads();
  if (tid == 0) {
    float cst = 0.f;
    for (int c=0;c<CG;++c) cst += s_c1p[c];
    s_cst = cst;
  }
  // ---- Phase D6: effective single-output 5x5 kernel ----
  for (int o = tid; o < CG*25; o += NT) {
    int ci = o / 25, k = o % 25;
    int dh = k / 5, dw = k % 5;
    float wv = 0.f;
    for (int c=0;c<CG;++c) wv += s_a3[c] * w5[(c*CG+ci)*25 + k];
    if (dh>=1 && dh<=3 && dw>=1 && dw<=3) {
      int k3 = (dh-1)*3 + (dw-1);
      for (int c=0;c<CG;++c) wv += s_a2[c] * w3[(c*CG+ci)*9 + k3];
    }
    s_Wc[ci][k] = wv;
  }
  // ---- Phase D7: fold k1 into h-gate ----
  for (int o = tid; o < CG*HH; o += NT) {
    int ci = o >> 6;
    s_sh[o] *= s_k1[ci];
  }

  // ---- Phase E: row-pair conv, register-software-pipelined tile refill ----
  // warp wid owns output rows h0..h0+7; lane owns cols lane, lane+32.
  float acc[16];
  #pragma unroll
  for (int i=0;i<16;++i) acc[i] = 0.f;
  const int h0 = wid * 8;

  float4 pre[4];
  #pragma unroll
  for (int k=0;k<4;++k) pre[k] = gx4[tid + NT*k];   // tile 0

  for (int ci = 0; ci < CG; ++ci) {
    __syncthreads();                            // prev iter's tile reads complete
    #pragma unroll
    for (int k=0;k<4;++k) {
      int f = tid + NT*k;                       // float4 index 0..1023
      int h = f >> 4, w4 = f & 15;
      *reinterpret_cast<float4*>(s_tile + (h+2)*TSTR + 4 + w4*4) = pre[k];
    }
    __syncthreads();                            // tile ci visible to all
    if (ci + 1 < CG) {
      const float4* nsrc = reinterpret_cast<const float4*>(gx + (ci+1)*HW);
      #pragma unroll
      for (int k=0;k<4;++k) pre[k] = nsrc[tid + NT*k];  // hidden behind compute
    }

    float wc[25];
    #pragma unroll
    for (int k=0;k<25;++k) wc[k] = s_Wc[ci][k];
    float sw0 = s_sw[ci*WW + lane];
    float sw1 = s_sw[ci*WW + lane + 32];
    #pragma unroll
    for (int jp = 0; jp < 4; ++jp) {            // row pairs: shared 6-row window
      int h = h0 + jp*2;
      float kh0 = s_sh[ci*HH + h];
      float kh1 = s_sh[ci*HH + h + 1];
      float a00=0.f,a01=0.f,a10=0.f,a11=0.f;
      #pragma unroll
      for (int r = 0; r < 6; ++r) {
        const float* trow = s_tile + (h + r)*TSTR + 2;
        float v0[5], v1[5];
        #pragma unroll
        for (int d=0; d<5; ++d) { v0[d] = trow[lane + d]; v1[d] = trow[lane + 32 + d]; }
        if (r < 5) {
          #pragma unroll
          for (int d=0; d<5; ++d) { a00 += wc[r*5+d]*v0[d]; a01 += wc[r*5+d]*v1[d]; }
        }
        if (r >= 1) {
          #pragma unroll
          for (int d=0; d<5; ++d) { a10 += wc[(r-1)*5+d]*v0[d]; a11 += wc[(r-1)*5+d]*v1[d]; }
        }
      }
      float c00 = s_tile[(h+2)*TSTR + 4 + lane];
      float c01 = s_tile[(h+2)*TSTR + 4 + lane + 32];
      float c10 = s_tile[(h+3)*TSTR + 4 + lane];
      float c11 = s_tile[(h+3)*TSTR + 4 + lane + 32];
      a00 += kh0*sw0*c00;  a01 += kh0*sw1*c01;
      a10 += kh1*sw0*c10;  a11 += kh1*sw1*c11;
      acc[jp*4+0]+=a00; acc[jp*4+1]+=a01; acc[jp*4+2]+=a10; acc[jp*4+3]+=a11;
    }
  }

  // ---- Phase F: out = x * ca[ci] * sigmoid(wsum) ----
  float cst = s_cst;
  float wv[16];
  #pragma unroll
  for (int i=0;i<16;++i) wv[i] = sigf(acc[i] + cst);
  for (int ci = 0; ci < CG; ++ci) {
    float cav = s_ca[ci];
    #pragma unroll
    for (int jp=0;jp<4;++jp) {
      int h = h0 + jp*2;
      int b = ci*HW + h*WW + lane;
      gout[b]    = gx[b]    * (cav * wv[jp*4+0]);
      gout[b+32] = gx[b+32] * (cav * wv[jp*4+1]);
      gout[b+64] = gx[b+64] * (cav * wv[jp*4+2]);
      gout[b+96] = gx[b+96] * (cav * wv[jp*4+3]);
    }
  }
}

extern "C" void kernel_launch(void* const* d_in, const int* in_sizes, int n_in,
                              void* d_out, int out_size) {
  (void)in_sizes; (void)n_in; (void)out_size;
  cudaFuncSetAttribute(ema_kernel, cudaFuncAttributeMaxDynamicSharedMemorySize, DYN_BYTES);
  ema_kernel<<<NGROUPS, NT, DYN_BYTES>>>(
      (const float*)d_in[0],
      (const float*)d_in[1], (const float*)d_in[2],
      (const float*)d_in[3], (const float*)d_in[4],
      (const float*)d_in[5], (const float*)d_in[6],
      (const float*)d_in[7], (const float*)d_in[8],
      (const float*)d_in[9], (const float*)d_in[10],
      (float*)d_out);
}